// round 6
// baseline (speedup 1.0000x reference)
#include <cuda_runtime.h>

// ---------------------------------------------------------------------------
// Drifter: x_{n+1} = x_n + drift(x_n)*20, 100 steps, T=101 samples stored.
// drift(x) = Re( P(e^{ix}) ), P(z) = sum_f (cw[f] - i*sw[f]) z^f (complex Horner).
// 4 batch elements per thread as TWO independent f32x2 chains -> ILP=2 to hide
// the serial per-step FFMA/MUFU latency chain (the R0 bottleneck: issue=20.7%).
// Outputs: out[0:B*T] = t_mesh, out[B*T:2BT] = xt wrapped to [-pi,pi).
// xt staged in smem in 16-step chunks; flush uses ALL 32 lanes (lo half -> xt,
// hi half -> t_mesh), fully coalesced.
// ---------------------------------------------------------------------------

typedef unsigned long long u64;

__device__ __forceinline__ u64 pk2(float lo, float hi) {
    u64 r; asm("mov.b64 %0, {%1, %2};" : "=l"(r) : "f"(lo), "f"(hi)); return r;
}
__device__ __forceinline__ float2 upk2(u64 v) {
    float2 f; asm("mov.b64 {%0, %1}, %2;" : "=f"(f.x), "=f"(f.y) : "l"(v)); return f;
}
__device__ __forceinline__ u64 fma2(u64 a, u64 b, u64 c) {
    u64 d; asm("fma.rn.f32x2 %0, %1, %2, %3;" : "=l"(d) : "l"(a), "l"(b), "l"(c)); return d;
}
__device__ __forceinline__ u64 mul2(u64 a, u64 b) {
    u64 d; asm("mul.rn.f32x2 %0, %1, %2;" : "=l"(d) : "l"(a), "l"(b)); return d;
}

#define FS      8
#define T_PTS   101
#define DT_F    20.0f
#define TPB     128
#define NCH     2            // independent f32x2 chains per thread
#define EPB     (TPB * 2 * NCH)   // 512 elements per block
#define CHUNK   16           // time-steps staged in smem per flush

__device__ __forceinline__ float wrapf(float x) {
    // (x + pi) mod 2pi - pi  ==  x - 2pi * floor(x/(2pi) + 0.5)
    float k = floorf(__fmaf_rn(x, 0.15915494309189535f, 0.5f));
    return __fmaf_rn(k, -6.283185307179586f, x);
}

__global__ void __launch_bounds__(TPB, 6)
drifter_kernel(const float* __restrict__ x0,
               const float* __restrict__ sw,
               const float* __restrict__ cw,
               float* __restrict__ out, int B)
{
    const int T = T_PTS;
    float* out_t = out;                       // t_mesh [B, T]
    float* out_x = out + (size_t)B * T;       // xt     [B, T]

    __shared__ float stage[EPB][CHUNK + 1];   // 512 x 17 floats = 34.8 KB

    const int tid  = threadIdx.x;
    const size_t base = (size_t)blockIdx.x * EPB;

    // chain c owns elements base + c*256 + {tid, tid+128}
    u64 x2[NCH];
#pragma unroll
    for (int c = 0; c < NCH; ++c) {
        const size_t e0 = base + (size_t)(c * 2 * TPB) + tid;
        const size_t e1 = e0 + TPB;
        float xa = (e0 < (size_t)B) ? x0[e0] : 0.0f;
        float xb = (e1 < (size_t)B) ? x0[e1] : 0.0f;
        x2[c] = pk2(xa, xb);
    }

    // Packed (broadcast) coefficients: CWp[f] = cw[f], NSWp[f] = -sw[f]
    u64 CWp[FS], NSWp[FS];
#pragma unroll
    for (int f = 0; f < FS; ++f) {
        float cv = __ldg(cw + f);
        float sv = __ldg(sw + f);
        CWp[f]  = pk2(cv, cv);
        NSWp[f] = pk2(-sv, -sv);
    }
    const u64 NEG1 = pk2(-1.0f, -1.0f);
    const u64 DT2  = pk2(DT_F, DT_F);

    for (int chunk = 0; chunk < T; chunk += CHUNK) {
        const int clen = min(CHUNK, T - chunk);

        // ---- compute clen samples into the stage buffer (2 chains interleave) ----
        for (int s = 0; s < clen; ++s) {
#pragma unroll
            for (int c = 0; c < NCH; ++c) {
                float2 xv = upk2(x2[c]);
                const int r0 = c * 2 * TPB + tid;
                stage[r0][s]       = wrapf(xv.x);
                stage[r0 + TPB][s] = wrapf(xv.y);

                float sa, ca, sb, cb;
                __sincosf(xv.x, &sa, &ca);
                __sincosf(xv.y, &sb, &cb);
                u64 zr  = pk2(ca, cb);
                u64 zi  = pk2(sa, sb);
                u64 nzi = mul2(zi, NEG1);

                // complex Horner over f = 7..0 (only Re needed at f=0)
                u64 ar = CWp[FS - 1], ai = NSWp[FS - 1];
#pragma unroll
                for (int f = FS - 2; f >= 1; --f) {
                    u64 tr = fma2(ai, nzi, CWp[f]);   // -ai*zi + cw_f
                    u64 ti = fma2(ai, zr,  NSWp[f]);  //  ai*zr - sw_f
                    u64 nr = fma2(ar, zr,  tr);
                    ai     = fma2(ar, zi,  ti);
                    ar     = nr;
                }
                u64 tr    = fma2(ai, nzi, CWp[0]);
                u64 drift = fma2(ar, zr,  tr);
                x2[c] = fma2(drift, DT2, x2[c]);      // x += drift * 20
            }
        }

        __syncthreads();

        // ---- coalesced flush: full warp active.
        // lanes 0-15  store xt  columns [chunk, chunk+clen)
        // lanes 16-31 store t_mesh, same columns ----
        const int warp = tid >> 5;
        const int lane = tid & 31;
        const int l15  = lane & 15;
        const bool is_t = lane >= 16;
        if (l15 < clen) {
            const int col = chunk + l15;
            const float tval = DT_F * (float)col;
            float* bp = (is_t ? out_t : out_x) + col;
#pragma unroll 8
            for (int r = warp; r < EPB; r += 4) {
                const size_t row = base + (size_t)r;
                if (row < (size_t)B)
                    bp[row * (size_t)T] = is_t ? tval : stage[r][l15];
            }
        }
        __syncthreads();
    }
}

extern "C" void kernel_launch(void* const* d_in, const int* in_sizes, int n_in,
                              void* d_out, int out_size)
{
    const float* x0 = (const float*)d_in[0];   // x0_sample [B]
    const float* sw = (const float*)d_in[1];   // sin_weight [8]
    const float* cw = (const float*)d_in[2];   // cos_weight [8]
    // d_in[3] (t_sample) does not affect the output.
    const int B = in_sizes[0];
    const int blocks = (B + EPB - 1) / EPB;    // 2048 for B = 1048576
    drifter_kernel<<<blocks, TPB>>>(x0, sw, cw, (float*)d_out, B);
}

// round 7
// speedup vs baseline: 2.3738x; 2.3738x over previous
#include <cuda_runtime.h>

// ---------------------------------------------------------------------------
// Drifter: x_{n+1} = x_n + drift(x_n)*20, 100 steps, T=101 samples stored.
// drift(x) = Re( P(e^{ix}) ), P(z) = sum_f (cw[f] - i*sw[f]) z^f (complex Horner).
// One f32x2-packed chain per thread (2 elements) — the R0 structure that
// benched 483us. Changes vs R0:
//   * CHUNK 32->16: smem 17.4KB -> 8 blocks/SM (occ 36% -> 50%)
//   * t_mesh written once, up front, outside the barrier-bounded loop
//   * flush: 2 rows x 16 cols per warp store -> all 32 lanes active
// ---------------------------------------------------------------------------

typedef unsigned long long u64;

__device__ __forceinline__ u64 pk2(float lo, float hi) {
    u64 r; asm("mov.b64 %0, {%1, %2};" : "=l"(r) : "f"(lo), "f"(hi)); return r;
}
__device__ __forceinline__ float2 upk2(u64 v) {
    float2 f; asm("mov.b64 {%0, %1}, %2;" : "=f"(f.x), "=f"(f.y) : "l"(v)); return f;
}
__device__ __forceinline__ u64 fma2(u64 a, u64 b, u64 c) {
    u64 d; asm("fma.rn.f32x2 %0, %1, %2, %3;" : "=l"(d) : "l"(a), "l"(b), "l"(c)); return d;
}
__device__ __forceinline__ u64 mul2(u64 a, u64 b) {
    u64 d; asm("mul.rn.f32x2 %0, %1, %2;" : "=l"(d) : "l"(a), "l"(b)); return d;
}

#define FS      8
#define T_PTS   101
#define DT_F    20.0f
#define TPB     128
#define EPB     256   // elements per block (2 per thread, one packed chain)
#define CHUNK   16    // time-steps staged in smem per flush

__device__ __forceinline__ float wrapf(float x) {
    // (x + pi) mod 2pi - pi  ==  x - 2pi * floor(x/(2pi) + 0.5)
    float k = floorf(__fmaf_rn(x, 0.15915494309189535f, 0.5f));
    return __fmaf_rn(k, -6.283185307179586f, x);
}

__global__ void __launch_bounds__(TPB, 8)
drifter_kernel(const float* __restrict__ x0,
               const float* __restrict__ sw,
               const float* __restrict__ cw,
               float* __restrict__ out, int B)
{
    const int T = T_PTS;
    float* out_t = out;                       // t_mesh [B, T]
    float* out_x = out + (size_t)B * T;       // xt     [B, T]

    __shared__ float stage[EPB][CHUNK + 1];   // 256 x 17 floats = 17.4 KB

    const int tid  = threadIdx.x;
    const int warp = tid >> 5;
    const int lane = tid & 31;
    const size_t base = (size_t)blockIdx.x * EPB;

    // ---- phase 0: t_mesh (compute-independent, coalesced 128B warp stores) ----
    {
        for (int r = warp; r < EPB; r += 4) {
            const size_t row = base + (size_t)r;
            if (row < (size_t)B) {
                float* pt = out_t + row * (size_t)T;
#pragma unroll
                for (int s = lane; s < T; s += 32)
                    pt[s] = DT_F * (float)s;
            }
        }
    }

    // ---- phase 1: integrate + staged xt flush ----
    const size_t e0 = base + tid;
    const size_t e1 = e0 + TPB;
    float xa = (e0 < (size_t)B) ? x0[e0] : 0.0f;
    float xb = (e1 < (size_t)B) ? x0[e1] : 0.0f;
    u64 x2 = pk2(xa, xb);

    // Packed (broadcast) coefficients: CWp[f] = cw[f], NSWp[f] = -sw[f]
    u64 CWp[FS], NSWp[FS];
#pragma unroll
    for (int f = 0; f < FS; ++f) {
        float c = __ldg(cw + f);
        float s = __ldg(sw + f);
        CWp[f]  = pk2(c, c);
        NSWp[f] = pk2(-s, -s);
    }
    const u64 NEG1 = pk2(-1.0f, -1.0f);
    const u64 DT2  = pk2(DT_F, DT_F);

    for (int chunk = 0; chunk < T; chunk += CHUNK) {
        const int clen = min(CHUNK, T - chunk);

        // ---- compute clen samples into the stage buffer ----
        for (int s = 0; s < clen; ++s) {
            float2 xv = upk2(x2);
            stage[tid][s]       = wrapf(xv.x);
            stage[tid + TPB][s] = wrapf(xv.y);

            // advance one Euler step (one extra harmless step after j=100)
            float sa, ca, sb, cb;
            __sincosf(xv.x, &sa, &ca);
            __sincosf(xv.y, &sb, &cb);
            u64 zr  = pk2(ca, cb);
            u64 zi  = pk2(sa, sb);
            u64 nzi = mul2(zi, NEG1);

            // complex Horner: acc = W7; acc = acc*z + Wf  (f = 6..1)
            u64 ar = CWp[FS - 1], ai = NSWp[FS - 1];
#pragma unroll
            for (int f = FS - 2; f >= 1; --f) {
                u64 tr = fma2(ai, nzi, CWp[f]);   // -ai*zi + cw_f
                u64 ti = fma2(ai, zr,  NSWp[f]);  //  ai*zr - sw_f
                u64 nr = fma2(ar, zr,  tr);
                ai     = fma2(ar, zi,  ti);
                ar     = nr;
            }
            // f = 0: only the real part is needed
            u64 tr    = fma2(ai, nzi, CWp[0]);
            u64 drift = fma2(ar, zr,  tr);
            x2 = fma2(drift, DT2, x2);            // x += drift * 20
        }

        __syncthreads();

        // ---- flush xt: each warp store = 2 rows x 16 cols, all lanes on ----
        {
            const int col  = lane & 15;          // column within chunk
            const int half = lane >> 4;          // row parity within pair
            if (col < clen) {
#pragma unroll 8
                for (int k = 0; k < EPB / 8; ++k) {   // 32 iterations
                    const int r = warp * 2 + half + k * 8;
                    const size_t row = base + (size_t)r;
                    if (row < (size_t)B)
                        out_x[row * (size_t)T + chunk + col] = stage[r][col];
                }
            }
        }
        __syncthreads();
    }
}

extern "C" void kernel_launch(void* const* d_in, const int* in_sizes, int n_in,
                              void* d_out, int out_size)
{
    const float* x0 = (const float*)d_in[0];   // x0_sample [B]
    const float* sw = (const float*)d_in[1];   // sin_weight [8]
    const float* cw = (const float*)d_in[2];   // cos_weight [8]
    // d_in[3] (t_sample) does not affect the output.
    const int B = in_sizes[0];
    const int blocks = (B + EPB - 1) / EPB;    // 4096 for B = 1048576
    drifter_kernel<<<blocks, TPB>>>(x0, sw, cw, (float*)d_out, B);
}